// round 14
// baseline (speedup 1.0000x reference)
#include <cuda_runtime.h>
#include <cstdint>

// Problem constants
#define Bsz 4
#define Tsz 4096
#define Isz 2048
#define Esz 16
#define Jsz 128
#define Csz 1024

#define BM 128
#define BN 128
#define BK 64
#define NTHREADS 128            // 4 warps: 2 (M) x 2 (N), warp tile 64x64
#define NITER (Isz / BK)        // 32
#define PITCH 36                // u32 per row: 32 data (64 fp16) + 4 pad
#define TILE_U32 (BM * PITCH)   // 4608
#define STAGE_U32 (2 * TILE_U32)          // A tile + B tile
#define DYN_SMEM (2 * STAGE_U32 * 4)      // 73728 B (2 stages)

__device__ __forceinline__ uint32_t pack_f16x2(float lo, float hi) {
    uint32_t r;
    asm("cvt.rn.f16x2.f32 %0, %1, %2;" : "=r"(r) : "f"(hi), "f"(lo));
    return r;
}

__device__ __forceinline__ void sts64(uint32_t addr, uint32_t x, uint32_t y) {
    asm volatile("st.shared.v2.b32 [%0], {%1,%2};" :: "r"(addr), "r"(x), "r"(y) : "memory");
}

__device__ __forceinline__ void ldsm_x4(uint32_t& r0, uint32_t& r1, uint32_t& r2,
                                        uint32_t& r3, uint32_t addr) {
    asm volatile("ldmatrix.sync.aligned.m8n8.x4.shared.b16 {%0,%1,%2,%3}, [%4];"
                 : "=r"(r0), "=r"(r1), "=r"(r2), "=r"(r3) : "r"(addr));
}

__device__ __forceinline__ void mma_f16(float c[4], const uint32_t a[4], const uint32_t b[2]) {
    asm volatile(
        "mma.sync.aligned.m16n8k16.row.col.f32.f16.f16.f32 "
        "{%0,%1,%2,%3}, {%4,%5,%6,%7}, {%8,%9}, {%0,%1,%2,%3};\n"
        : "+f"(c[0]), "+f"(c[1]), "+f"(c[2]), "+f"(c[3])
        : "r"(a[0]), "r"(a[1]), "r"(a[2]), "r"(a[3]), "r"(b[0]), "r"(b[1]));
}

__global__ void __launch_bounds__(NTHREADS, 2)
gather_gemm_f16(const float* __restrict__ X,
                const void* __restrict__ ind_raw,
                const float* __restrict__ W,
                float* __restrict__ out)
{
    extern __shared__ uint32_t smem[];   // [2 stages][A(128x36) | B(128x36)] u32
    __shared__ int sIdx[BM];
    __shared__ int sIs64;

    const int mtile = blockIdx.x;   // 0..7
    const int e     = blockIdx.y;   // 0..15
    const int b     = blockIdx.z;   // 0..3
    const int tid   = threadIdx.x;
    const int lane  = tid & 31;
    const int warp  = tid >> 5;
    const int wm    = warp & 1;     // 0..1
    const int wn    = warp >> 1;    // 0..1

    const uint32_t smemAddr = (uint32_t)__cvta_generic_to_shared(smem);

    // ---- dtype sniff: int64 vs int32 indices (values < 4096 -> int64 odd words zero)
    if (warp == 0) {
        const uint32_t* iw = (const uint32_t*)ind_raw;
        uint32_t oddw = iw[2 * lane + 1];
        unsigned mask = __ballot_sync(0xFFFFFFFFu, oddw == 0u);
        if (lane == 0) sIs64 = (mask == 0xFFFFFFFFu) ? 1 : 0;
    }
    __syncthreads();
    const int is64 = sIs64;

    {
        size_t p = ((size_t)b * Esz + e) * Csz + (size_t)mtile * BM + tid;
        int t;
        if (is64) t = (int)((const long long*)ind_raw)[p];
        else      t = ((const int*)ind_raw)[p];
        sIdx[tid] = t;
    }
    __syncthreads();

    const float* Xb = X + (size_t)b * Tsz * Isz;
    const float* Wb = W + (size_t)e * Jsz * Isz;

    // producer: 8 threads per row; thread covers 8 A rows + 8 B rows (trow+16r),
    // two 16B fp32 chunks per row (cols c4 and c4+32) per BK=64 tile.
    const int trow = tid >> 3;        // 0..15
    const int u    = tid & 7;
    const int c4   = u * 4;           // float col of chunk 0
    const int h2   = u * 2;           // u32 col in fp16 row for chunk 0

    uint32_t aOff[8], bOff[8];        // 32-bit gmem float offsets (chunk 0)
    uint32_t stsA[8], stsB[8];        // smem byte addrs within stage 0 (chunk 0)
#pragma unroll
    for (int r = 0; r < 8; r++) {
        int m = trow + r * 16;
        aOff[r] = (uint32_t)(sIdx[m] * Isz + c4);
        bOff[r] = (uint32_t)(m * Isz + c4);
        stsA[r] = smemAddr + (uint32_t)((m * PITCH + h2) * 4);
        stsB[r] = smemAddr + (uint32_t)((TILE_U32 + m * PITCH + h2) * 4);
    }
    // chunk 1 (k-cols +32 floats) sits +16 u32 = +64 B in smem, +32 floats in gmem.

    float acc[4][8][4];
#pragma unroll
    for (int i = 0; i < 4; i++)
#pragma unroll
        for (int j = 0; j < 8; j++)
#pragma unroll
            for (int r = 0; r < 4; r++) acc[i][j][r] = 0.0f;

    const int g = lane >> 2;   // 0..7
    const int q = lane & 3;    // 0..3

    // ldmatrix per-thread addresses (within stage 0), validated in R13:
    const int aRow = wm * 64 + (lane & 15);
    const int aCol = (lane >> 4) * 4;               // u32
    const uint32_t ldsmA0 = smemAddr + (uint32_t)((aRow * PITCH + aCol) * 4);
    const int bRow = wn * 64 + ((lane >> 4) << 3) + (lane & 7);
    const int bCol = ((lane >> 3) & 1) * 4;         // u32
    const uint32_t ldsmB0 = smemAddr + (uint32_t)((TILE_U32 + bRow * PITCH + bCol) * 4);

    float4 st[8];   // one chunk of staging (32 regs), reused 4x per iter

#define LDG_CHUNK(BASE, OFFS, COLADD)                                         \
    {                                                                         \
        _Pragma("unroll")                                                     \
        for (int r = 0; r < 8; r++)                                           \
            st[r] = *(const float4*)((BASE) + (OFFS)[r] + (COLADD));          \
    }
#define STS_CHUNK(ADDRS, BYTEADD)                                             \
    {                                                                         \
        _Pragma("unroll")                                                     \
        for (int r = 0; r < 8; r++)                                           \
            sts64((ADDRS)[r] + (BYTEADD),                                     \
                  pack_f16x2(st[r].x, st[r].y), pack_f16x2(st[r].z, st[r].w)); \
    }

    // ---- prologue: fill stage 0 with tile 0 (all 4 chunks)
    LDG_CHUNK(Xb, aOff, 0);        STS_CHUNK(stsA, 0);
    LDG_CHUNK(Xb, aOff, 32);       STS_CHUNK(stsA, 64);
    LDG_CHUNK(Wb, bOff, 0);        STS_CHUNK(stsB, 0);
    LDG_CHUNK(Wb, bOff, 32);       STS_CHUNK(stsB, 64);
    __syncthreads();

    for (int it = 0; it < NITER; it++) {
        const uint32_t cOff = (uint32_t)((it & 1) * STAGE_U32 * 4);        // compute stage
        const uint32_t tOff = (uint32_t)(((it + 1) & 1) * STAGE_U32 * 4);  // fill target
        const int k0 = (it + 1) * BK;
        const bool fill = (it + 1 < NITER);

        // 4 k16-steps; producer chunks threaded between MMA blocks.
        // Fill target stage was last read by compute(it-1), which completed
        // before the barrier at the end of iter it-1 -> WAR safe without an
        // extra barrier. Visibility for compute(it+1) comes from the barrier
        // at the end of this iteration.
#pragma unroll
        for (int ks = 0; ks < 4; ks++) {
            const uint32_t kOff = cOff + (uint32_t)(ks * 32);   // 8 u32 per k16
            uint32_t areg[4][4];
            uint32_t breg[8][2];
#pragma unroll
            for (int i = 0; i < 4; i++)
                ldsm_x4(areg[i][0], areg[i][1], areg[i][2], areg[i][3],
                        ldsmA0 + kOff + (uint32_t)(i * 16 * PITCH * 4));
#pragma unroll
            for (int jp = 0; jp < 4; jp++)
                ldsm_x4(breg[2 * jp][0], breg[2 * jp][1],
                        breg[2 * jp + 1][0], breg[2 * jp + 1][1],
                        ldsmB0 + kOff + (uint32_t)(jp * 16 * PITCH * 4));

            if (fill) {
                if (ks == 0) { LDG_CHUNK(Xb, aOff, k0); }
                if (ks == 1) { STS_CHUNK(stsA, tOff);      LDG_CHUNK(Xb, aOff, k0 + 32); }
                if (ks == 2) { STS_CHUNK(stsA, tOff + 64); LDG_CHUNK(Wb, bOff, k0); }
                if (ks == 3) { STS_CHUNK(stsB, tOff);      LDG_CHUNK(Wb, bOff, k0 + 32); }
            }

#pragma unroll
            for (int i = 0; i < 4; i++)
#pragma unroll
                for (int j = 0; j < 8; j++)
                    mma_f16(acc[i][j], areg[i], breg[j]);
        }
        if (fill) { STS_CHUNK(stsB, tOff + 64); }

        __syncthreads();
    }

    // ---- epilogue (fp16 RN is unbiased: no correction factor)
    float* outp = out + (((size_t)b * Esz + e) * Csz + (size_t)mtile * BM) * Jsz;
#pragma unroll
    for (int i = 0; i < 4; i++) {
        int row0 = wm * 64 + i * 16 + g;
#pragma unroll
        for (int j = 0; j < 8; j++) {
            int col = wn * 64 + j * 8 + 2 * q;
            *(float2*)(outp + (size_t)row0 * Jsz + col) =
                make_float2(acc[i][j][0], acc[i][j][1]);
            *(float2*)(outp + (size_t)(row0 + 8) * Jsz + col) =
                make_float2(acc[i][j][2], acc[i][j][3]);
        }
    }
}

extern "C" void kernel_launch(void* const* d_in, const int* in_sizes, int n_in,
                              void* d_out, int out_size)
{
    const float* X   = (const float*)d_in[0];
    const void*  ind = (const void*)d_in[1];
    const float* W   = (const float*)d_in[2];
    float* out = (float*)d_out;

    cudaFuncSetAttribute(gather_gemm_f16,
                         cudaFuncAttributeMaxDynamicSharedMemorySize, DYN_SMEM);

    dim3 grid(Csz / BM, Esz, Bsz);   // (8, 16, 4) = 512 CTAs
    dim3 block(NTHREADS);
    gather_gemm_f16<<<grid, block, DYN_SMEM>>>(X, ind, W, out);
}

// round 15
// speedup vs baseline: 1.3005x; 1.3005x over previous
#include <cuda_runtime.h>
#include <cuda_fp16.h>
#include <cstdint>

// Problem constants
#define Bsz 4
#define Tsz 4096
#define Isz 2048
#define Esz 16
#define Jsz 128
#define Csz 1024

#define BM 128
#define BN 128
#define BK 32
#define NTHREADS 128            // 4 warps: 2 (M) x 2 (N), warp tile 64x64
#define NITER (Isz / BK)        // 64
#define STAGES 4
#define PITCH 20                // u32 per smem row: 16 data (32 fp16) + 4 pad
#define ROW_BYTES (PITCH * 4)   // 80
#define ATILE_BYTES (BM * ROW_BYTES)      // 10240
#define STAGE_BYTES (2 * ATILE_BYTES)     // 20480 (A + B)
#define DYN_SMEM (STAGES * STAGE_BYTES)   // 81920

// fp16 scratch (module-load allocation; sanctioned scratch mechanism)
__device__ __align__(16) __half g_X16[Bsz * Tsz * Isz];   // 64 MB
__device__ __align__(16) __half g_W16[Esz * Jsz * Isz];   // 8 MB

__device__ __forceinline__ uint32_t pack_f16x2(float lo, float hi) {
    uint32_t r;
    asm("cvt.rn.f16x2.f32 %0, %1, %2;" : "=r"(r) : "f"(hi), "f"(lo));
    return r;
}

__device__ __forceinline__ void cp_async16(uint32_t smem_addr, const void* gptr) {
    asm volatile("cp.async.cg.shared.global [%0], [%1], 16;\n"
                 :: "r"(smem_addr), "l"(gptr));
}
__device__ __forceinline__ void cp_commit() {
    asm volatile("cp.async.commit_group;\n" ::: "memory");
}
template <int N>
__device__ __forceinline__ void cp_wait() {
    asm volatile("cp.async.wait_group %0;\n" :: "n"(N) : "memory");
}

__device__ __forceinline__ void ldsm_x4(uint32_t& r0, uint32_t& r1, uint32_t& r2,
                                        uint32_t& r3, uint32_t addr) {
    asm volatile("ldmatrix.sync.aligned.m8n8.x4.shared.b16 {%0,%1,%2,%3}, [%4];"
                 : "=r"(r0), "=r"(r1), "=r"(r2), "=r"(r3) : "r"(addr));
}

__device__ __forceinline__ void mma_f16(float c[4], const uint32_t a[4], const uint32_t b[2]) {
    asm volatile(
        "mma.sync.aligned.m16n8k16.row.col.f32.f16.f16.f32 "
        "{%0,%1,%2,%3}, {%4,%5,%6,%7}, {%8,%9}, {%0,%1,%2,%3};\n"
        : "+f"(c[0]), "+f"(c[1]), "+f"(c[2]), "+f"(c[3])
        : "r"(a[0]), "r"(a[1]), "r"(a[2]), "r"(a[3]), "r"(b[0]), "r"(b[1]));
}

// ---- pre-pass: fp32 -> fp16 for X and W (grid-stride over float4) ----
__global__ void convert_f16(const float4* __restrict__ X4, const float4* __restrict__ W4)
{
    const int NX4 = (Bsz * Tsz * Isz) / 4;   // 8388608
    const int NW4 = (Esz * Jsz * Isz) / 4;   // 1048576
    uint2* __restrict__ x16 = (uint2*)g_X16;
    uint2* __restrict__ w16 = (uint2*)g_W16;
    const int stride = gridDim.x * blockDim.x;
    for (int i = blockIdx.x * blockDim.x + threadIdx.x; i < NX4; i += stride) {
        float4 v = X4[i];
        x16[i] = make_uint2(pack_f16x2(v.x, v.y), pack_f16x2(v.z, v.w));
    }
    for (int i = blockIdx.x * blockDim.x + threadIdx.x; i < NW4; i += stride) {
        float4 v = W4[i];
        w16[i] = make_uint2(pack_f16x2(v.x, v.y), pack_f16x2(v.z, v.w));
    }
}

// ---- main: gathered fp16 GEMM, cp.async 4-stage ring + ldmatrix consumer ----
__global__ void __launch_bounds__(NTHREADS, 2)
gather_gemm_f16(const void* __restrict__ ind_raw, float* __restrict__ out)
{
    extern __shared__ uint32_t smem[];   // [STAGES][A(128x20) | B(128x20)] u32
    __shared__ int sIdx[BM];
    __shared__ int sIs64;

    const int mtile = blockIdx.x;   // 0..7
    const int e     = blockIdx.y;   // 0..15
    const int b     = blockIdx.z;   // 0..3
    const int tid   = threadIdx.x;
    const int lane  = tid & 31;
    const int warp  = tid >> 5;
    const int wm    = warp & 1;     // 0..1
    const int wn    = warp >> 1;    // 0..1

    const uint32_t smemAddr = (uint32_t)__cvta_generic_to_shared(smem);

    // ---- dtype sniff: int64 vs int32 indices (values < 4096 -> int64 odd words zero)
    if (warp == 0) {
        const uint32_t* iw = (const uint32_t*)ind_raw;
        uint32_t oddw = iw[2 * lane + 1];
        unsigned mask = __ballot_sync(0xFFFFFFFFu, oddw == 0u);
        if (lane == 0) sIs64 = (mask == 0xFFFFFFFFu) ? 1 : 0;
    }
    __syncthreads();
    const int is64 = sIs64;

    {
        size_t p = ((size_t)b * Esz + e) * Csz + (size_t)mtile * BM + tid;
        int t;
        if (is64) t = (int)((const long long*)ind_raw)[p];
        else      t = ((const int*)ind_raw)[p];
        sIdx[tid] = t;
    }
    __syncthreads();

    const __half* Xb = g_X16 + (size_t)b * Tsz * Isz;
    const __half* Wb = g_W16 + (size_t)e * Jsz * Isz;

    // producer: thread covers 4 A rows + 4 B rows (trow2 + 32r), one 16B chunk
    // (8 fp16) per row at chunk index u4.
    const int trow2 = tid >> 2;       // 0..31
    const int u4    = tid & 3;        // chunk within 64B row segment

    uint32_t aH[4], bH[4];            // gmem half-offsets (chunk 0 of tile k0=0)
    uint32_t csA[4], csB[4];          // smem byte addrs within stage 0
#pragma unroll
    for (int r = 0; r < 4; r++) {
        int m = trow2 + r * 32;
        aH[r] = (uint32_t)(sIdx[m] * Isz + u4 * 8);
        bH[r] = (uint32_t)(m * Isz + u4 * 8);
        csA[r] = smemAddr + (uint32_t)(m * ROW_BYTES + u4 * 16);
        csB[r] = smemAddr + (uint32_t)(ATILE_BYTES + m * ROW_BYTES + u4 * 16);
    }

    float acc[4][8][4];
#pragma unroll
    for (int i = 0; i < 4; i++)
#pragma unroll
        for (int j = 0; j < 8; j++)
#pragma unroll
            for (int r = 0; r < 4; r++) acc[i][j][r] = 0.0f;

    const int g = lane >> 2;   // 0..7
    const int q = lane & 3;    // 0..3

    // ldmatrix per-thread addresses (within stage 0) — validated in R13:
    const int aRow = wm * 64 + (lane & 15);
    const int aCol = (lane >> 4) * 4;               // u32
    const uint32_t ldsmA0 = smemAddr + (uint32_t)((aRow * PITCH + aCol) * 4);
    const int bRow = wn * 64 + ((lane >> 4) << 3) + (lane & 7);
    const int bCol = ((lane >> 3) & 1) * 4;         // u32
    const uint32_t ldsmB0 = smemAddr + (uint32_t)((ATILE_BYTES / 4 + bRow * PITCH + bCol) * 4);

#define ISSUE_STAGE(S, K0)                                                    \
    {                                                                         \
        const uint32_t _o = (uint32_t)((S) * STAGE_BYTES);                    \
        _Pragma("unroll")                                                     \
        for (int r = 0; r < 4; r++) {                                         \
            cp_async16(csA[r] + _o, Xb + aH[r] + (K0));                       \
            cp_async16(csB[r] + _o, Wb + bH[r] + (K0));                       \
        }                                                                     \
        cp_commit();                                                          \
    }

    // ---- prologue: stages 0..2
    ISSUE_STAGE(0, 0);
    ISSUE_STAGE(1, BK);
    ISSUE_STAGE(2, 2 * BK);

    int sc = 0;   // stage being computed
    int si = 3;   // stage being issued
    for (int it = 0; it < NITER; it++) {
        // per-thread wait, then barrier -> ALL threads' copies for stage sc visible
        cp_wait<2>();
        __syncthreads();

        // issue stage it+3 (that buffer was computed at it-1; WAR fenced by the
        // barrier above)
        if (it + 3 < NITER) {
            ISSUE_STAGE(si, (it + 3) * BK);
        }

        const uint32_t sOff = (uint32_t)(sc * STAGE_BYTES);

        // 2 k16-steps per BK=32
#pragma unroll
        for (int ks = 0; ks < 2; ks++) {
            const uint32_t kOff = sOff + (uint32_t)(ks * 32);   // 8 u32 = 32 B
            uint32_t areg[4][4];
            uint32_t breg[8][2];
#pragma unroll
            for (int i = 0; i < 4; i++)
                ldsm_x4(areg[i][0], areg[i][1], areg[i][2], areg[i][3],
                        ldsmA0 + kOff + (uint32_t)(i * 16 * ROW_BYTES));
#pragma unroll
            for (int jp = 0; jp < 4; jp++)
                ldsm_x4(breg[2 * jp][0], breg[2 * jp][1],
                        breg[2 * jp + 1][0], breg[2 * jp + 1][1],
                        ldsmB0 + kOff + (uint32_t)(jp * 16 * ROW_BYTES));
#pragma unroll
            for (int i = 0; i < 4; i++)
#pragma unroll
                for (int j = 0; j < 8; j++)
                    mma_f16(acc[i][j], areg[i], breg[j]);
        }

        if (++sc == STAGES) sc = 0;
        if (++si == STAGES) si = 0;
    }

    // ---- epilogue (fp16 RN unbiased; no correction)
    float* outp = out + (((size_t)b * Esz + e) * Csz + (size_t)mtile * BM) * Jsz;
#pragma unroll
    for (int i = 0; i < 4; i++) {
        int row0 = wm * 64 + i * 16 + g;
#pragma unroll
        for (int j = 0; j < 8; j++) {
            int col = wn * 64 + j * 8 + 2 * q;
            *(float2*)(outp + (size_t)row0 * Jsz + col) =
                make_float2(acc[i][j][0], acc[i][j][1]);
            *(float2*)(outp + (size_t)(row0 + 8) * Jsz + col) =
                make_float2(acc[i][j][2], acc[i][j][3]);
        }
    }
}

extern "C" void kernel_launch(void* const* d_in, const int* in_sizes, int n_in,
                              void* d_out, int out_size)
{
    const float* X   = (const float*)d_in[0];
    const void*  ind = (const void*)d_in[1];
    const float* W   = (const float*)d_in[2];
    float* out = (float*)d_out;

    // pre-pass: fp32 -> fp16 (stream-ordered before the GEMM)
    convert_f16<<<2048, 256>>>((const float4*)X, (const float4*)W);

    cudaFuncSetAttribute(gather_gemm_f16,
                         cudaFuncAttributeMaxDynamicSharedMemorySize, DYN_SMEM);

    dim3 grid(Csz / BM, Esz, Bsz);   // (8, 16, 4) = 512 CTAs
    dim3 block(NTHREADS);
    gather_gemm_f16<<<grid, block, DYN_SMEM>>>(ind, out);
}

// round 16
// speedup vs baseline: 1.4881x; 1.1442x over previous
#include <cuda_runtime.h>
#include <cuda_fp16.h>
#include <cstdint>

// Problem constants
#define Bsz 4
#define Tsz 4096
#define Isz 2048
#define Esz 16
#define Jsz 128
#define Csz 1024

#define BM 128
#define BN 128
#define BK 32
#define NTHREADS 128            // 4 warps: 2 (M) x 2 (N), warp tile 64x64
#define NITER (Isz / BK)        // 64
#define BSTAGES 4
#define PITCH 20                // u32 per smem row: 16 data (32 fp16) + 4 pad
#define ROW_BYTES (PITCH * 4)   // 80
#define TILE_BYTES (BM * ROW_BYTES)       // 10240
#define B_BASE (2 * TILE_BYTES)           // A double buffer first
#define DYN_SMEM (B_BASE + BSTAGES * TILE_BYTES)   // 61440

// fp16 W scratch (module-load allocation; sanctioned scratch mechanism)
__device__ __align__(16) __half g_W16[Esz * Jsz * Isz];   // 8 MB

__device__ __forceinline__ uint32_t pack_f16x2(float lo, float hi) {
    uint32_t r;
    asm("cvt.rn.f16x2.f32 %0, %1, %2;" : "=r"(r) : "f"(hi), "f"(lo));
    return r;
}

__device__ __forceinline__ void sts64(uint32_t addr, uint32_t x, uint32_t y) {
    asm volatile("st.shared.v2.b32 [%0], {%1,%2};" :: "r"(addr), "r"(x), "r"(y) : "memory");
}

__device__ __forceinline__ void cp_async16(uint32_t smem_addr, const void* gptr) {
    asm volatile("cp.async.cg.shared.global [%0], [%1], 16;\n"
                 :: "r"(smem_addr), "l"(gptr));
}
__device__ __forceinline__ void cp_commit() {
    asm volatile("cp.async.commit_group;\n" ::: "memory");
}
template <int N>
__device__ __forceinline__ void cp_wait() {
    asm volatile("cp.async.wait_group %0;\n" :: "n"(N) : "memory");
}

__device__ __forceinline__ void ldsm_x4(uint32_t& r0, uint32_t& r1, uint32_t& r2,
                                        uint32_t& r3, uint32_t addr) {
    asm volatile("ldmatrix.sync.aligned.m8n8.x4.shared.b16 {%0,%1,%2,%3}, [%4];"
                 : "=r"(r0), "=r"(r1), "=r"(r2), "=r"(r3) : "r"(addr));
}

__device__ __forceinline__ void mma_f16(float c[4], const uint32_t a[4], const uint32_t b[2]) {
    asm volatile(
        "mma.sync.aligned.m16n8k16.row.col.f32.f16.f16.f32 "
        "{%0,%1,%2,%3}, {%4,%5,%6,%7}, {%8,%9}, {%0,%1,%2,%3};\n"
        : "+f"(c[0]), "+f"(c[1]), "+f"(c[2]), "+f"(c[3])
        : "r"(a[0]), "r"(a[1]), "r"(a[2]), "r"(a[3]), "r"(b[0]), "r"(b[1]));
}

// ---- pre-pass: fp32 -> fp16 for W only (48 MB stream, ~4 us) ----
__global__ void convert_w16(const float4* __restrict__ W4)
{
    const int NW4 = (Esz * Jsz * Isz) / 4;   // 1048576
    uint2* __restrict__ w16 = (uint2*)g_W16;
    const int stride = gridDim.x * blockDim.x;
    for (int i = blockIdx.x * blockDim.x + threadIdx.x; i < NW4; i += stride) {
        float4 v = W4[i];
        w16[i] = make_uint2(pack_f16x2(v.x, v.y), pack_f16x2(v.z, v.w));
    }
}

// ---- main: gathered fp16 GEMM; A = in-kernel cvt (2-stage), B = cp.async ring ----
__global__ void __launch_bounds__(NTHREADS, 2)
gather_gemm_f16(const float* __restrict__ X,
                const void* __restrict__ ind_raw,
                float* __restrict__ out)
{
    extern __shared__ uint32_t smem[];   // [A s0][A s1][B s0..3], 10240 B each
    __shared__ int sIdx[BM];
    __shared__ int sIs64;

    const int mtile = blockIdx.x;   // 0..7
    const int e     = blockIdx.y;   // 0..15
    const int b     = blockIdx.z;   // 0..3
    const int tid   = threadIdx.x;
    const int lane  = tid & 31;
    const int warp  = tid >> 5;
    const int wm    = warp & 1;     // 0..1
    const int wn    = warp >> 1;    // 0..1

    const uint32_t smemAddr = (uint32_t)__cvta_generic_to_shared(smem);

    // ---- dtype sniff: int64 vs int32 indices (values < 4096 -> int64 odd words zero)
    if (warp == 0) {
        const uint32_t* iw = (const uint32_t*)ind_raw;
        uint32_t oddw = iw[2 * lane + 1];
        unsigned mask = __ballot_sync(0xFFFFFFFFu, oddw == 0u);
        if (lane == 0) sIs64 = (mask == 0xFFFFFFFFu) ? 1 : 0;
    }
    __syncthreads();
    const int is64 = sIs64;

    {
        size_t p = ((size_t)b * Esz + e) * Csz + (size_t)mtile * BM + tid;
        int t;
        if (is64) t = (int)((const long long*)ind_raw)[p];
        else      t = ((const int*)ind_raw)[p];
        sIdx[tid] = t;
    }
    __syncthreads();

    const float*  Xb = X + (size_t)b * Tsz * Isz;
    const __half* Wb = g_W16 + (size_t)e * Jsz * Isz;

    // ---- A producer (fp32 LDG + cvt + STS, 2-stage): thread covers 8 rows
    // (trow + 16r), one 16B fp32 chunk per row.
    const int trow = tid >> 3;        // 0..15
    const int c4   = (tid & 7) * 4;   // float col within BK

    uint32_t aOff[8];                 // gmem float offsets
    uint32_t stsA[8];                 // smem byte addrs within A stage 0
#pragma unroll
    for (int r = 0; r < 8; r++) {
        int m = trow + r * 16;
        aOff[r] = (uint32_t)(sIdx[m] * Isz + c4);
        stsA[r] = smemAddr + (uint32_t)(m * ROW_BYTES + (tid & 7) * 8);
    }

    // ---- B producer (cp.async from g_W16, 4-stage): thread covers 4 rows
    // (trow2 + 32r), one 16B chunk (8 fp16) per row.
    const int trow2 = tid >> 2;       // 0..31
    const int u4    = tid & 3;

    uint32_t bH[4];                   // gmem half-offsets
    uint32_t csB[4];                  // smem byte addrs within B stage 0
#pragma unroll
    for (int r = 0; r < 4; r++) {
        int m = trow2 + r * 32;
        bH[r]  = (uint32_t)(m * Isz + u4 * 8);
        csB[r] = smemAddr + (uint32_t)(B_BASE + m * ROW_BYTES + u4 * 16);
    }

    float acc[4][8][4];
#pragma unroll
    for (int i = 0; i < 4; i++)
#pragma unroll
        for (int j = 0; j < 8; j++)
#pragma unroll
            for (int r = 0; r < 4; r++) acc[i][j][r] = 0.0f;

    const int g = lane >> 2;   // 0..7
    const int q = lane & 3;    // 0..3

    // ldmatrix per-thread addresses — validated R13/R15:
    const int aRow = wm * 64 + (lane & 15);
    const int aCol = (lane >> 4) * 4;               // u32
    const uint32_t ldsmA0 = smemAddr + (uint32_t)(aRow * ROW_BYTES + aCol * 4);
    const int bRow = wn * 64 + ((lane >> 4) << 3) + (lane & 7);
    const int bCol = ((lane >> 3) & 1) * 4;         // u32
    const uint32_t ldsmB0 = smemAddr + (uint32_t)(B_BASE + bRow * ROW_BYTES + bCol * 4);

#define ISSUE_B(S, K0)                                                        \
    {                                                                         \
        const uint32_t _o = (uint32_t)((S) * TILE_BYTES);                     \
        _Pragma("unroll")                                                     \
        for (int r = 0; r < 4; r++)                                           \
            cp_async16(csB[r] + _o, Wb + bH[r] + (K0));                       \
        cp_commit();                                                          \
    }

    // ---- prologue: A tile 0 -> regs; B stages 0..2 in flight
    float4 ra[8];
#pragma unroll
    for (int r = 0; r < 8; r++) ra[r] = *(const float4*)(Xb + aOff[r]);
    ISSUE_B(0, 0);
    ISSUE_B(1, BK);
    ISSUE_B(2, 2 * BK);

    for (int it = 0; it < NITER; it++) {
        const uint32_t aSt = (uint32_t)((it & 1) * TILE_BYTES);
        const int bS = it & 3;

        // A: store tile it (cvt on the way), prefetch tile it+1.
        // WAR: laggard warps are in compute(it-1) on A stage (it-1)&1 != it&1.
#pragma unroll
        for (int r = 0; r < 8; r++)
            sts64(stsA[r] + aSt, pack_f16x2(ra[r].x, ra[r].y),
                                 pack_f16x2(ra[r].z, ra[r].w));
        if (it + 1 < NITER) {
            const int k0 = (it + 1) * BK;
#pragma unroll
            for (int r = 0; r < 8; r++)
                ra[r] = *(const float4*)(Xb + aOff[r] + k0);
        }

        // B: per-thread wait, then barrier -> all copies for stage bS visible.
        // The same barrier publishes this iteration's A-tile STS.
        cp_wait<2>();
        __syncthreads();

        // issue B stage it+3 (that buffer was consumed at it-1; WAR fenced by
        // the barrier above) — R15-identical ordering.
        if (it + 3 < NITER) {
            ISSUE_B((it + 3) & 3, (it + 3) * BK);
        }

        const uint32_t bOff = (uint32_t)(bS * TILE_BYTES);

        // 2 k16-steps per BK=32
#pragma unroll
        for (int ks = 0; ks < 2; ks++) {
            const uint32_t kB = (uint32_t)(ks * 32);   // 8 u32 = 32 B
            uint32_t areg[4][4];
            uint32_t breg[8][2];
#pragma unroll
            for (int i = 0; i < 4; i++)
                ldsm_x4(areg[i][0], areg[i][1], areg[i][2], areg[i][3],
                        ldsmA0 + aSt + kB + (uint32_t)(i * 16 * ROW_BYTES));
#pragma unroll
            for (int jp = 0; jp < 4; jp++)
                ldsm_x4(breg[2 * jp][0], breg[2 * jp][1],
                        breg[2 * jp + 1][0], breg[2 * jp + 1][1],
                        ldsmB0 + bOff + kB + (uint32_t)(jp * 16 * ROW_BYTES));
#pragma unroll
            for (int i = 0; i < 4; i++)
#pragma unroll
                for (int j = 0; j < 8; j++)
                    mma_f16(acc[i][j], areg[i], breg[j]);
        }
    }

    // ---- epilogue (fp16 RN unbiased; no correction)
    float* outp = out + (((size_t)b * Esz + e) * Csz + (size_t)mtile * BM) * Jsz;
#pragma unroll
    for (int i = 0; i < 4; i++) {
        int row0 = wm * 64 + i * 16 + g;
#pragma unroll
        for (int j = 0; j < 8; j++) {
            int col = wn * 64 + j * 8 + 2 * q;
            *(float2*)(outp + (size_t)row0 * Jsz + col) =
                make_float2(acc[i][j][0], acc[i][j][1]);
            *(float2*)(outp + (size_t)(row0 + 8) * Jsz + col) =
                make_float2(acc[i][j][2], acc[i][j][3]);
        }
    }
}

extern "C" void kernel_launch(void* const* d_in, const int* in_sizes, int n_in,
                              void* d_out, int out_size)
{
    const float* X   = (const float*)d_in[0];
    const void*  ind = (const void*)d_in[1];
    const float* W   = (const float*)d_in[2];
    float* out = (float*)d_out;

    // pre-pass: W fp32 -> fp16 only (~48 MB stream)
    convert_w16<<<1024, 256>>>((const float4*)W);

    cudaFuncSetAttribute(gather_gemm_f16,
                         cudaFuncAttributeMaxDynamicSharedMemorySize, DYN_SMEM);

    dim3 grid(Csz / BM, Esz, Bsz);   // (8, 16, 4) = 512 CTAs
    dim3 block(NTHREADS);
    gather_gemm_f16<<<grid, block, DYN_SMEM>>>(X, ind, out);
}